// round 11
// baseline (speedup 1.0000x reference)
#include <cuda_runtime.h>

#define Bv 8
#define Cv 128
#define Hv 128
#define Wv 128
#define KK 9
#define NPLANES (Bv * Cv)
#define CONV_CTAS 740   /* 148 SMs x 5 */

// Scratch (no allocations allowed in kernel_launch)
__device__ float g_pooled[Bv * Cv];
__device__ float g_h[Bv * Cv];
__device__ unsigned int g_ctr;
__device__ unsigned int g_done[Bv];
__device__ volatile unsigned int g_hdone[Bv];

// ---- cp.async helpers -------------------------------------------------------
__device__ __forceinline__ void cp_async16(unsigned smem_addr, const void* gptr) {
    asm volatile("cp.async.cg.shared.global [%0], [%1], 16;"
                 :: "r"(smem_addr), "l"(gptr));
}
__device__ __forceinline__ void cp_async_wait_all() {
    asm volatile("cp.async.commit_group;");
    asm volatile("cp.async.wait_group 0;");
}

// ---------------------------------------------------------------------------
// Kernel 0: reset pipeline state (graph replays need fresh state every call).
// ---------------------------------------------------------------------------
__global__ void init_kernel() {
    if (threadIdx.x < Bv) {
        g_done[threadIdx.x] = 0;
        g_hdone[threadIdx.x] = 0;
    }
    if (threadIdx.x == 0) g_ctr = 0;
}

// ---------------------------------------------------------------------------
// Kernel 1: persistent pipelined pool -> h -> kern+conv.
// Work items 0..1023   : pool plane i (batch-major), direct-LDG reduce.
// Work items 1024..2047: conv plane, staged into smem in 2 half-plane tiles
//                        via cp.async.cg (33KB in flight per CTA per burst).
// ---------------------------------------------------------------------------
__global__ void __launch_bounds__(256, 5)
mega_kernel(const float* __restrict__ x,
            const float* __restrict__ w1, const float* __restrict__ b1,
            const float* __restrict__ w2, const float* __restrict__ b2,
            float* __restrict__ out) {
    const int tid = threadIdx.x;
    const int wid = tid >> 5;       // 0..7
    const int lane = tid & 31;

    __shared__ float s[66][128];    // 64-row half-plane + top/bottom halo rows
    __shared__ unsigned int s_item;
    __shared__ int s_do_h;
    __shared__ float sdata[8];
    __shared__ float kw[KK];

    for (;;) {
        if (tid == 0) s_item = atomicAdd(&g_ctr, 1u);
        __syncthreads();
        const unsigned int item = s_item;
        if (item >= 2u * NPLANES) break;

        if (item < NPLANES) {
            // ================= POOL (+ maybe h) =================
            const int plane = item;
            const int b = plane >> 7;
            const float4* xp = (const float4*)(x + (size_t)plane * Hv * Wv);

            float sum = 0.f;
#pragma unroll
            for (int i = 0; i < 16; i++) {
                float4 v = xp[tid + i * 256];
                sum += (v.x + v.y) + (v.z + v.w);
            }
#pragma unroll
            for (int o = 16; o; o >>= 1) sum += __shfl_down_sync(0xffffffffu, sum, o);
            if (lane == 0) sdata[wid] = sum;
            __syncthreads();
            if (tid == 0) {
                float t = sdata[0];
#pragma unroll
                for (int i = 1; i < 8; i++) t += sdata[i];
                g_pooled[plane] = t * (1.f / (float)(Hv * Wv));
                __threadfence();
                const unsigned int d = atomicAdd(&g_done[b], 1u);
                s_do_h = (d == Cv - 1);
            }
            __syncthreads();

            if (s_do_h) {
                __threadfence();  // observe all 128 pooled writes
                const float4 pv = __ldcg((const float4*)(g_pooled + b * Cv) + lane);
#pragma unroll 4
                for (int i = 0; i < 16; i++) {
                    const int o = wid * 16 + i;
                    const float4 wv = __ldg((const float4*)(w1 + (size_t)o * Cv) + lane);
                    float acc = wv.x * pv.x;
                    acc = fmaf(wv.y, pv.y, acc);
                    acc = fmaf(wv.z, pv.z, acc);
                    acc = fmaf(wv.w, pv.w, acc);
#pragma unroll
                    for (int sft = 16; sft; sft >>= 1) acc += __shfl_xor_sync(0xffffffffu, acc, sft);
                    if (lane == 0) g_h[b * Cv + o] = fmaxf(acc + b1[o], 0.f);
                }
                __syncthreads();
                if (tid == 0) {
                    __threadfence();
                    g_hdone[b] = 1u;   // release flag
                }
            }
        } else {
            // ================= KERN TAPS + CONV =================
            const int plane = item - NPLANES;
            const int b = plane >> 7;
            const int c = plane & 127;

            if (tid == 0) {
                while (g_hdone[b] == 0u) __nanosleep(64);
            }
            __syncthreads();
            __threadfence();  // acquire before g_h reads

            {
                const float4 hv = __ldcg((const float4*)(g_h + b * Cv) + lane);
#pragma unroll
                for (int rep = 0; rep < 2; rep++) {
                    const int p = wid + rep * 8;
                    if (p < KK) {
                        const float4 wv = __ldg((const float4*)(w2 + (size_t)(c * KK + p) * Cv) + lane);
                        float acc = wv.x * hv.x;
                        acc = fmaf(wv.y, hv.y, acc);
                        acc = fmaf(wv.z, hv.z, acc);
                        acc = fmaf(wv.w, hv.w, acc);
#pragma unroll
                        for (int sft = 16; sft; sft >>= 1) acc += __shfl_xor_sync(0xffffffffu, acc, sft);
                        if (lane == 0) kw[p] = acc + b2[c * KK + p];
                    }
                }
            }
            __syncthreads();

            float w[9];
#pragma unroll
            for (int p = 0; p < 9; p++) w[p] = kw[p];

            const float* xp = x + (size_t)plane * Hv * Wv;
            float* op = out + (size_t)plane * Hv * Wv;

            // Two half-plane tiles of 64 output rows each.
#pragma unroll 1
            for (int half = 0; half < 2; half++) {
                const int gh0 = half * 64;

                // ---- stage 66 rows (gh0-1 .. gh0+64) into s[0..65] ----
                // 66 rows x 32 quads = 2112 16B transfers, 256 threads.
                for (int i = tid; i < 66 * 32; i += 256) {
                    const int r = i >> 5;
                    const int q = i & 31;
                    const int gr = gh0 + r - 1;
                    if (gr >= 0 && gr < Hv) {
                        unsigned sa = (unsigned)__cvta_generic_to_shared(&s[r][q * 4]);
                        cp_async16(sa, xp + gr * Wv + q * 4);
                    } else {
                        *(float4*)&s[r][q * 4] = make_float4(0.f, 0.f, 0.f, 0.f);
                    }
                }
                cp_async_wait_all();
                __syncthreads();

                // ---- each warp convolves 8 output rows from smem ----
                const int lr0 = wid * 8;   // local row of first output in this half

                // Expand smem row sr -> 6-float register row with column halo.
#define EXPAND(a, sr)                                                          \
                {                                                              \
                    float4 v = *(const float4*)&s[(sr)][lane * 4];             \
                    float cm1 = __shfl_up_sync(0xffffffffu, v.w, 1);           \
                    float cp4 = __shfl_down_sync(0xffffffffu, v.x, 1);         \
                    if (lane == 0) cm1 = 0.f;                                  \
                    if (lane == 31) cp4 = 0.f;                                 \
                    a[0] = cm1; a[1] = v.x; a[2] = v.y;                        \
                    a[3] = v.z; a[4] = v.w; a[5] = cp4;                        \
                }
#define OUTROW(gr, X, Y, Z)                                                    \
                {                                                              \
                    float4 o;                                                  \
                    float* po = &o.x;                                          \
                    _Pragma("unroll")                                          \
                    for (int k = 0; k < 4; k++) {                              \
                        float acc = X[k] * w[0];                               \
                        acc = fmaf(X[k + 1], w[1], acc);                       \
                        acc = fmaf(X[k + 2], w[2], acc);                       \
                        acc = fmaf(Y[k],     w[3], acc);                       \
                        acc = fmaf(Y[k + 1], w[4], acc);                       \
                        acc = fmaf(Y[k + 2], w[5], acc);                       \
                        acc = fmaf(Z[k],     w[6], acc);                       \
                        acc = fmaf(Z[k + 1], w[7], acc);                       \
                        acc = fmaf(Z[k + 2], w[8], acc);                       \
                        po[k] = acc;                                           \
                    }                                                          \
                    __stcs((float4*)(op + (gr) * Wv) + lane, o);               \
                }

                float R[3][6];
                EXPAND(R[0], lr0);
                EXPAND(R[1], lr0 + 1);
#pragma unroll
                for (int i = 0; i < 8; i++) {
                    EXPAND(R[(i + 2) % 3], lr0 + i + 2);
                    OUTROW(gh0 + lr0 + i, R[i % 3], R[(i + 1) % 3], R[(i + 2) % 3]);
                }
#undef EXPAND
#undef OUTROW

                __syncthreads();   // tile reuse barrier before next half
            }
        }
    }
}

// ---------------------------------------------------------------------------
extern "C" void kernel_launch(void* const* d_in, const int* in_sizes, int n_in,
                              void* d_out, int out_size) {
    const float* x  = (const float*)d_in[0];
    const float* w1 = (const float*)d_in[1];
    const float* b1 = (const float*)d_in[2];
    const float* w2 = (const float*)d_in[3];
    const float* b2 = (const float*)d_in[4];
    float* out = (float*)d_out;

    init_kernel<<<1, 32>>>();
    mega_kernel<<<CONV_CTAS, 256>>>(x, w1, b1, w2, b2, out);
}